// round 2
// baseline (speedup 1.0000x reference)
#include <cuda_runtime.h>
#include <math.h>

#define B_  8
#define T_  2048
#define C_  1024
#define H_  128
#define BT_ (B_*T_)

// Scratch for projected Q,K,V (allocation-free rule: device globals)
__device__ float g_q[BT_*H_];
__device__ float g_k[BT_*H_];
__device__ float g_v[BT_*H_];

// ---------------------------------------------------------------------------
// Kernel 1: QKV projection.  out[m, h] = sum_c x[m, c] * W[h, c]
// Classic 64x64 tile SGEMM, 256 threads, 4x4 micro-tile, K-tile = 16.
// grid = (BT/64, 6)  where blockIdx.y selects {Wq,Wk,Wv} x {lo64, hi64}
// ---------------------------------------------------------------------------
__global__ __launch_bounds__(256) void qkv_kernel(
    const float* __restrict__ x,
    const float* __restrict__ Wq,
    const float* __restrict__ Wk,
    const float* __restrict__ Wv)
{
    __shared__ __align__(16) float As[16][64];   // [k][m]
    __shared__ __align__(16) float Bs[16][64];   // [k][n]

    const int tid   = threadIdx.x;
    const int m0    = blockIdx.x * 64;
    const int ybl   = blockIdx.y;          // 0..5
    const int head  = ybl >> 1;            // 0=Q,1=K,2=V
    const int nloc0 = (ybl & 1) * 64;      // column offset within head (0 or 64)

    const float* __restrict__ W  = (head == 0) ? Wq : (head == 1) ? Wk : Wv;
    float* __restrict__ outp     = (head == 0) ? g_q : (head == 1) ? g_k : g_v;

    const int lm = tid >> 2;        // 0..63  (row of the tile this thread loads)
    const int lk = (tid & 3) * 4;   // 0,4,8,12

    const int ty = tid >> 4;        // 0..15
    const int tx = tid & 15;        // 0..15

    float acc[4][4];
#pragma unroll
    for (int i = 0; i < 4; i++)
#pragma unroll
        for (int j = 0; j < 4; j++) acc[i][j] = 0.f;

    for (int k0 = 0; k0 < C_; k0 += 16) {
        float4 av = *(const float4*)&x[(size_t)(m0 + lm) * C_ + k0 + lk];
        float4 bv = *(const float4*)&W[(size_t)(nloc0 + lm) * C_ + k0 + lk];
        As[lk + 0][lm] = av.x; As[lk + 1][lm] = av.y;
        As[lk + 2][lm] = av.z; As[lk + 3][lm] = av.w;
        Bs[lk + 0][lm] = bv.x; Bs[lk + 1][lm] = bv.y;
        Bs[lk + 2][lm] = bv.z; Bs[lk + 3][lm] = bv.w;
        __syncthreads();

#pragma unroll
        for (int kk = 0; kk < 16; kk++) {
            float4 a4 = *(const float4*)&As[kk][ty * 4];
            float4 b4 = *(const float4*)&Bs[kk][tx * 4];
            float ar[4] = {a4.x, a4.y, a4.z, a4.w};
            float br[4] = {b4.x, b4.y, b4.z, b4.w};
#pragma unroll
            for (int i = 0; i < 4; i++)
#pragma unroll
                for (int j = 0; j < 4; j++)
                    acc[i][j] += ar[i] * br[j];
        }
        __syncthreads();
    }

#pragma unroll
    for (int i = 0; i < 4; i++) {
        float4 r = make_float4(acc[i][0], acc[i][1], acc[i][2], acc[i][3]);
        *(float4*)&outp[(size_t)(m0 + ty * 4 + i) * H_ + nloc0 + tx * 4] = r;
    }
}

// ---------------------------------------------------------------------------
// Kernel 2: causal flash attention, Br = Bc = 64, fp32 online softmax.
// grid = (T/64, B), 256 threads.
// Thread (ty,tx) owns S rows ty*4..+3 x cols tx*4..+3 and O rows ty*4..+3 x
// dims tx*8..+7.
// ---------------------------------------------------------------------------
struct AttnSmem {
    float Qs[128][64];     // k-major Q tile  (32 KB)
    float Ks[128][64];     // k-major K tile  (32 KB)
    float Vs[64][128];     // row-major V tile(32 KB)
    float Ps[64][68];      // transposed P, padded rows (17 KB)
    float sm_m[64];
    float sm_l[64];
    float sm_a[64];
};

__global__ __launch_bounds__(256) void attn_kernel(float* __restrict__ out)
{
    extern __shared__ __align__(16) char smem_raw[];
    AttnSmem& S = *reinterpret_cast<AttnSmem*>(smem_raw);

    const int tid = threadIdx.x;
    const int qt  = blockIdx.x;        // query tile 0..31
    const int b   = blockIdx.y;
    const int ty  = tid >> 4;          // 0..15
    const int tx  = tid & 15;          // 0..15
    const float scale = 0.08838834764831845f;   // 1/sqrt(128)

    const size_t qbase = ((size_t)b * T_ + (size_t)qt * 64) * H_;

    // Load Q tile transposed: Qs[k][r]
    {
        const int r  = tid >> 2;          // 0..63
        const int kq = (tid & 3) * 4;     // 0,4,8,12
#pragma unroll
        for (int it = 0; it < 8; it++) {
            const int k = kq + it * 16;
            float4 v = *(const float4*)&g_q[qbase + (size_t)r * H_ + k];
            S.Qs[k + 0][r] = v.x; S.Qs[k + 1][r] = v.y;
            S.Qs[k + 2][r] = v.z; S.Qs[k + 3][r] = v.w;
        }
    }
    if (tid < 64) { S.sm_m[tid] = -1e30f; S.sm_l[tid] = 0.f; }

    float o[4][8];
#pragma unroll
    for (int i = 0; i < 4; i++)
#pragma unroll
        for (int d = 0; d < 8; d++) o[i][d] = 0.f;

    for (int kt = 0; kt <= qt; kt++) {
        __syncthreads();   // prior iteration's Vs/Ps reads done; Q load done

        // Load K transposed + V direct
        const size_t kbase = ((size_t)b * T_ + (size_t)kt * 64) * H_;
        {
            const int r  = tid >> 2;
            const int kq = (tid & 3) * 4;
#pragma unroll
            for (int it = 0; it < 8; it++) {
                const int k = kq + it * 16;
                float4 v = *(const float4*)&g_k[kbase + (size_t)r * H_ + k];
                S.Ks[k + 0][r] = v.x; S.Ks[k + 1][r] = v.y;
                S.Ks[k + 2][r] = v.z; S.Ks[k + 3][r] = v.w;
            }
#pragma unroll
            for (int it = 0; it < 8; it++) {
                const int c = kq + it * 16;
                *(float4*)&S.Vs[r][c] =
                    *(const float4*)&g_v[kbase + (size_t)r * H_ + c];
            }
        }
        __syncthreads();

        // S = Q K^T   (each thread 4x4)
        float s[4][4];
#pragma unroll
        for (int i = 0; i < 4; i++)
#pragma unroll
            for (int j = 0; j < 4; j++) s[i][j] = 0.f;

        for (int k = 0; k < H_; k++) {
            float4 a4 = *(const float4*)&S.Qs[k][ty * 4];
            float4 b4 = *(const float4*)&S.Ks[k][tx * 4];
            float ar[4] = {a4.x, a4.y, a4.z, a4.w};
            float br[4] = {b4.x, b4.y, b4.z, b4.w};
#pragma unroll
            for (int i = 0; i < 4; i++)
#pragma unroll
                for (int j = 0; j < 4; j++)
                    s[i][j] += ar[i] * br[j];
        }

        // scale + causal mask + store transposed into Ps
        const int qr0 = qt * 64 + ty * 4;
        const int kc0 = kt * 64 + tx * 4;
#pragma unroll
        for (int i = 0; i < 4; i++)
#pragma unroll
            for (int j = 0; j < 4; j++) {
                float v = s[i][j] * scale;
                if (kc0 + j > qr0 + i) v = -1e30f;
                S.Ps[tx * 4 + j][ty * 4 + i] = v;
            }
        __syncthreads();

        // Online softmax: 4 threads per row, 16 cols each
        {
            const int row  = tid >> 2;
            const int part = tid & 3;
            float mx = -1e30f;
#pragma unroll
            for (int c = 0; c < 16; c++)
                mx = fmaxf(mx, S.Ps[part * 16 + c][row]);
            mx = fmaxf(mx, __shfl_xor_sync(0xffffffffu, mx, 1));
            mx = fmaxf(mx, __shfl_xor_sync(0xffffffffu, mx, 2));

            const float m_old = S.sm_m[row];
            const float m_new = fmaxf(m_old, mx);

            float sum = 0.f;
#pragma unroll
            for (int c = 0; c < 16; c++) {
                float p = __expf(S.Ps[part * 16 + c][row] - m_new);
                S.Ps[part * 16 + c][row] = p;
                sum += p;
            }
            sum += __shfl_xor_sync(0xffffffffu, sum, 1);
            sum += __shfl_xor_sync(0xffffffffu, sum, 2);

            if (part == 0) {
                float alpha = __expf(m_old - m_new);
                S.sm_a[row] = alpha;
                S.sm_m[row] = m_new;
                S.sm_l[row] = S.sm_l[row] * alpha + sum;
            }
        }
        __syncthreads();

        // Rescale O, then O += P V
        float al[4];
#pragma unroll
        for (int i = 0; i < 4; i++) al[i] = S.sm_a[ty * 4 + i];
#pragma unroll
        for (int i = 0; i < 4; i++)
#pragma unroll
            for (int d = 0; d < 8; d++) o[i][d] *= al[i];

        for (int c = 0; c < 64; c++) {
            float4 p4 = *(const float4*)&S.Ps[c][ty * 4];
            float4 v0 = *(const float4*)&S.Vs[c][tx * 8];
            float4 v1 = *(const float4*)&S.Vs[c][tx * 8 + 4];
            float pr[4] = {p4.x, p4.y, p4.z, p4.w};
            float vr[8] = {v0.x, v0.y, v0.z, v0.w, v1.x, v1.y, v1.z, v1.w};
#pragma unroll
            for (int i = 0; i < 4; i++)
#pragma unroll
                for (int d = 0; d < 8; d++)
                    o[i][d] += pr[i] * vr[d];
        }
    }

    // Final normalization + writeout
#pragma unroll
    for (int i = 0; i < 4; i++) {
        const float inv = 1.f / S.sm_l[ty * 4 + i];
        float4 r0 = make_float4(o[i][0] * inv, o[i][1] * inv,
                                o[i][2] * inv, o[i][3] * inv);
        float4 r1 = make_float4(o[i][4] * inv, o[i][5] * inv,
                                o[i][6] * inv, o[i][7] * inv);
        const size_t ob = qbase + (size_t)(ty * 4 + i) * H_ + tx * 8;
        *(float4*)&out[ob]     = r0;
        *(float4*)&out[ob + 4] = r1;
    }
}

// ---------------------------------------------------------------------------
extern "C" void kernel_launch(void* const* d_in, const int* in_sizes, int n_in,
                              void* d_out, int out_size)
{
    const float* x  = (const float*)d_in[0];
    const float* Wq = (const float*)d_in[1];
    const float* Wk = (const float*)d_in[2];
    const float* Wv = (const float*)d_in[3];
    float* out = (float*)d_out;

    // QKV projection
    {
        dim3 grid(BT_ / 64, 6);
        qkv_kernel<<<grid, 256>>>(x, Wq, Wk, Wv);
    }

    // Attention
    {
        static int smem_set = 0;
        const int smem_bytes = (int)sizeof(AttnSmem);
        if (!smem_set) {
            cudaFuncSetAttribute(attn_kernel,
                                 cudaFuncAttributeMaxDynamicSharedMemorySize,
                                 smem_bytes);
            smem_set = 1;
        }
        dim3 grid(T_ / 64, B_);
        attn_kernel<<<grid, 256, smem_bytes>>>(out);
    }
}

// round 7
// speedup vs baseline: 5.5714x; 5.5714x over previous
#include <cuda_runtime.h>
#include <math.h>

#define B_  8
#define T_  2048
#define C_  1024
#define H_  128
#define BT_ (B_*T_)

// Scratch for projected Q,K,V (tf32-rounded fp32)
__device__ float g_q[BT_*H_];
__device__ float g_k[BT_*H_];
__device__ float g_v[BT_*H_];

// ---------------------------------------------------------------------------
// helpers
// ---------------------------------------------------------------------------
__device__ __forceinline__ unsigned f2tf(float x) {
    unsigned r;
    asm("cvt.rna.tf32.f32 %0, %1;" : "=r"(r) : "f"(x));
    return r;
}
__device__ __forceinline__ float tfr(float x) { return __uint_as_float(f2tf(x)); }

__device__ __forceinline__ void mma_tf32(float* d, unsigned a0, unsigned a1,
                                         unsigned a2, unsigned a3,
                                         unsigned b0, unsigned b1) {
    asm volatile(
        "mma.sync.aligned.m16n8k8.row.col.f32.tf32.tf32.f32 "
        "{%0,%1,%2,%3},{%4,%5,%6,%7},{%8,%9},{%0,%1,%2,%3};"
        : "+f"(d[0]), "+f"(d[1]), "+f"(d[2]), "+f"(d[3])
        : "r"(a0), "r"(a1), "r"(a2), "r"(a3), "r"(b0), "r"(b1));
}

__device__ __forceinline__ void cp_async16(void* smem_dst, const void* gsrc) {
    unsigned s = (unsigned)__cvta_generic_to_shared(smem_dst);
    asm volatile("cp.async.cg.shared.global [%0], [%1], 16;" :: "r"(s), "l"(gsrc));
}
__device__ __forceinline__ void cp_commit() {
    asm volatile("cp.async.commit_group;");
}
__device__ __forceinline__ void cp_wait0() {
    asm volatile("cp.async.wait_group 0;");
}
__device__ __forceinline__ void cp_wait1() {
    asm volatile("cp.async.wait_group 1;");
}

// ---------------------------------------------------------------------------
// Kernel 1: QKV projection with mma.sync tf32.
// C[m,h] = sum_c x[m,c] * W[h,c];  A = x row-major, B = W (already k-contig
// per output col since W is [h][c] row-major -> col-major k x n).
// CTA tile 128m x 128n (full head), 8 warps, warp tile 32m x 64n, k-tile 32.
// grid = (BT/128, 3)
// ---------------------------------------------------------------------------
__global__ __launch_bounds__(256) void qkv_mma(
    const float* __restrict__ x,
    const float* __restrict__ Wq,
    const float* __restrict__ Wk,
    const float* __restrict__ Wv)
{
    __shared__ __align__(16) float As[128][36];   // x tile  [m][k]
    __shared__ __align__(16) float Bs[128][36];   // W tile  [n][k]

    const int tid  = threadIdx.x;
    const int lane = tid & 31;
    const int w    = tid >> 5;
    const int gid  = lane >> 2;      // 0..7
    const int tig  = lane & 3;       // 0..3

    const int head = blockIdx.y;
    const float* __restrict__ W = (head == 0) ? Wq : (head == 1) ? Wk : Wv;
    float* __restrict__ outp    = (head == 0) ? g_q : (head == 1) ? g_k : g_v;

    const size_t m0 = (size_t)blockIdx.x * 128;
    const int wm = (w >> 1) * 32;
    const int wn = (w & 1) * 64;

    // loader mapping: 8 lanes per row (32 floats = 8 float4)
    const int ar = tid >> 3;          // 0..31, rows ar + 32*i
    const int af = tid & 7;           // float4 index in row

    float acc[2][8][4];
#pragma unroll
    for (int mf = 0; mf < 2; mf++)
#pragma unroll
        for (int nt = 0; nt < 8; nt++)
#pragma unroll
            for (int j = 0; j < 4; j++) acc[mf][nt][j] = 0.f;

    float4 px[4], pw[4];

    // prefetch k-tile 0
#pragma unroll
    for (int i = 0; i < 4; i++) {
        px[i] = *(const float4*)&x[(m0 + ar + 32 * i) * C_ + 4 * af];
        pw[i] = *(const float4*)&W[(size_t)(ar + 32 * i) * C_ + 4 * af];
    }

    for (int k0 = 0; k0 < C_; k0 += 32) {
        __syncthreads();
#pragma unroll
        for (int i = 0; i < 4; i++) {
            const int r = ar + 32 * i;
            float4 a = px[i];
            float4 ca = make_float4(tfr(a.x), tfr(a.y), tfr(a.z), tfr(a.w));
            *(float4*)&As[r][4 * af] = ca;
            float4 b = pw[i];
            float4 cb = make_float4(tfr(b.x), tfr(b.y), tfr(b.z), tfr(b.w));
            *(float4*)&Bs[r][4 * af] = cb;
        }
        __syncthreads();

        if (k0 + 32 < C_) {
#pragma unroll
            for (int i = 0; i < 4; i++) {
                px[i] = *(const float4*)&x[(m0 + ar + 32 * i) * C_ + k0 + 32 + 4 * af];
                pw[i] = *(const float4*)&W[(size_t)(ar + 32 * i) * C_ + k0 + 32 + 4 * af];
            }
        }

#pragma unroll
        for (int ks = 0; ks < 4; ks++) {
            unsigned a[2][4];
#pragma unroll
            for (int mf = 0; mf < 2; mf++) {
                const int r = wm + mf * 16 + gid;
                a[mf][0] = __float_as_uint(As[r][ks * 8 + tig]);
                a[mf][1] = __float_as_uint(As[r + 8][ks * 8 + tig]);
                a[mf][2] = __float_as_uint(As[r][ks * 8 + tig + 4]);
                a[mf][3] = __float_as_uint(As[r + 8][ks * 8 + tig + 4]);
            }
#pragma unroll
            for (int nt = 0; nt < 8; nt++) {
                const int n = wn + nt * 8 + gid;
                unsigned b0 = __float_as_uint(Bs[n][ks * 8 + tig]);
                unsigned b1 = __float_as_uint(Bs[n][ks * 8 + tig + 4]);
                mma_tf32(acc[0][nt], a[0][0], a[0][1], a[0][2], a[0][3], b0, b1);
                mma_tf32(acc[1][nt], a[1][0], a[1][1], a[1][2], a[1][3], b0, b1);
            }
        }
    }

    // epilogue: tf32-round and store fp32
#pragma unroll
    for (int mf = 0; mf < 2; mf++) {
        const size_t r0 = m0 + wm + mf * 16 + gid;
#pragma unroll
        for (int nt = 0; nt < 8; nt++) {
            const int c = wn + nt * 8 + 2 * tig;
            float2 v0 = make_float2(tfr(acc[mf][nt][0]), tfr(acc[mf][nt][1]));
            *(float2*)&outp[r0 * H_ + c] = v0;
            float2 v1 = make_float2(tfr(acc[mf][nt][2]), tfr(acc[mf][nt][3]));
            *(float2*)&outp[(r0 + 8) * H_ + c] = v1;
        }
    }
}

// ---------------------------------------------------------------------------
// Kernel 2: causal flash attention with mma.sync tf32.
// Br = Bc = 64, 4 warps (128 thr), each warp owns 16 query rows.
// Q fragments + O accumulators register-resident. K/V double-buffered cp.async.
// Each CTA processes the balanced pair (qt = bx, qt = 31-bx): 33 iters always.
// grid = (16, 8)
// ---------------------------------------------------------------------------
struct AttnSmem {
    float Ks[2][64][132];   // K tiles (also Q staging in buf 0)
    float Vs[2][64][136];   // V tiles
    float Ps[4][16][68];    // per-warp P relayout buffer
};

__global__ __launch_bounds__(128) void attn_mma(float* __restrict__ out)
{
    extern __shared__ __align__(16) char smem_raw[];
    AttnSmem& S = *reinterpret_cast<AttnSmem*>(smem_raw);

    const int tid  = threadIdx.x;
    const int lane = tid & 31;
    const int w    = tid >> 5;       // 0..3
    const int gid  = lane >> 2;      // 0..7
    const int tig  = lane & 3;       // 0..3
    const int b    = blockIdx.y;
    const float scale = 0.08838834764831845f;   // 1/sqrt(128)

    const int lr = w + 4 * 0;  (void)lr;

    for (int pass = 0; pass < 2; pass++) {
        const int qt = (pass == 0) ? blockIdx.x : 31 - blockIdx.x;
        const size_t qbase = ((size_t)b * T_ + (size_t)qt * 64) * H_;

        // ---- stage Q tile into Ks[0], read A-fragments into registers ----
        __syncthreads();
#pragma unroll
        for (int i = 0; i < 16; i++) {
            const int r = w + 4 * i;
            cp_async16(&S.Ks[0][r][4 * lane], &g_q[qbase + (size_t)r * H_ + 4 * lane]);
        }
        cp_commit();
        cp_wait0();
        __syncthreads();

        unsigned qa[16][4];
        {
            const int rA = w * 16 + gid;
#pragma unroll
            for (int ks = 0; ks < 16; ks++) {
                qa[ks][0] = __float_as_uint(S.Ks[0][rA][ks * 8 + tig]);
                qa[ks][1] = __float_as_uint(S.Ks[0][rA + 8][ks * 8 + tig]);
                qa[ks][2] = __float_as_uint(S.Ks[0][rA][ks * 8 + tig + 4]);
                qa[ks][3] = __float_as_uint(S.Ks[0][rA + 8][ks * 8 + tig + 4]);
            }
        }
        __syncthreads();

        float o[16][4];
#pragma unroll
        for (int nt = 0; nt < 16; nt++)
#pragma unroll
            for (int j = 0; j < 4; j++) o[nt][j] = 0.f;
        float m_runA = -1e30f, m_runB = -1e30f;
        float l_runA = 0.f,    l_runB = 0.f;

        const int rowA = qt * 64 + w * 16 + gid;
        const int rowB = rowA + 8;

        // preload tile kt = 0
        {
            const size_t kb = ((size_t)b * T_) * H_ + (size_t)qt * 0;
            (void)kb;
            const size_t kb0 = ((size_t)b * T_ + 0) * H_;
#pragma unroll
            for (int i = 0; i < 16; i++) {
                const int r = w + 4 * i;
                cp_async16(&S.Ks[0][r][4 * lane], &g_k[kb0 + (size_t)r * H_ + 4 * lane]);
                cp_async16(&S.Vs[0][r][4 * lane], &g_v[kb0 + (size_t)r * H_ + 4 * lane]);
            }
            cp_commit();
        }

        for (int kt = 0; kt <= qt; kt++) {
            if (kt < qt) {
                const size_t kb = ((size_t)b * T_ + (size_t)(kt + 1) * 64) * H_;
                const int nb = (kt + 1) & 1;
#pragma unroll
                for (int i = 0; i < 16; i++) {
                    const int r = w + 4 * i;
                    cp_async16(&S.Ks[nb][r][4 * lane], &g_k[kb + (size_t)r * H_ + 4 * lane]);
                    cp_async16(&S.Vs[nb][r][4 * lane], &g_v[kb + (size_t)r * H_ + 4 * lane]);
                }
                cp_commit();
                cp_wait1();
            } else {
                cp_wait0();
            }
            __syncthreads();
            const int cur = kt & 1;

            // ---- S = Q K^T ----
            float s[8][4];
#pragma unroll
            for (int nt = 0; nt < 8; nt++)
#pragma unroll
                for (int j = 0; j < 4; j++) s[nt][j] = 0.f;

#pragma unroll
            for (int ks = 0; ks < 16; ks++) {
#pragma unroll
                for (int nt = 0; nt < 8; nt++) {
                    const int n = nt * 8 + gid;
                    unsigned b0 = __float_as_uint(S.Ks[cur][n][ks * 8 + tig]);
                    unsigned b1 = __float_as_uint(S.Ks[cur][n][ks * 8 + tig + 4]);
                    mma_tf32(s[nt], qa[ks][0], qa[ks][1], qa[ks][2], qa[ks][3], b0, b1);
                }
            }

            // ---- scale + causal mask ----
#pragma unroll
            for (int nt = 0; nt < 8; nt++)
#pragma unroll
                for (int j = 0; j < 4; j++) s[nt][j] *= scale;

            if (kt == qt) {
#pragma unroll
                for (int nt = 0; nt < 8; nt++) {
                    const int c0 = kt * 64 + nt * 8 + 2 * tig;
                    if (c0     > rowA) s[nt][0] = -1e30f;
                    if (c0 + 1 > rowA) s[nt][1] = -1e30f;
                    if (c0     > rowB) s[nt][2] = -1e30f;
                    if (c0 + 1 > rowB) s[nt][3] = -1e30f;
                }
            }

            // ---- per-warp online softmax (rows owned by quad groups) ----
            float mA = -1e30f, mB = -1e30f;
#pragma unroll
            for (int nt = 0; nt < 8; nt++) {
                mA = fmaxf(mA, fmaxf(s[nt][0], s[nt][1]));
                mB = fmaxf(mB, fmaxf(s[nt][2], s[nt][3]));
            }
            mA = fmaxf(mA, __shfl_xor_sync(0xffffffffu, mA, 1));
            mA = fmaxf(mA, __shfl_xor_sync(0xffffffffu, mA, 2));
            mB = fmaxf(mB, __shfl_xor_sync(0xffffffffu, mB, 1));
            mB = fmaxf(mB, __shfl_xor_sync(0xffffffffu, mB, 2));

            const float mnA = fmaxf(m_runA, mA);
            const float mnB = fmaxf(m_runB, mB);
            const float aA  = __expf(m_runA - mnA);
            const float aB  = __expf(m_runB - mnB);
            m_runA = mnA; m_runB = mnB;

            float sumA = 0.f, sumB = 0.f;
#pragma unroll
            for (int nt = 0; nt < 8; nt++) {
                float p0 = __expf(s[nt][0] - mnA);
                float p1 = __expf(s[nt][1] - mnA);
                float p2 = __expf(s[nt][2] - mnB);
                float p3 = __expf(s[nt][3] - mnB);
                sumA += p0 + p1;
                sumB += p2 + p3;
                *(float2*)&S.Ps[w][gid][nt * 8 + 2 * tig]     = make_float2(tfr(p0), tfr(p1));
                *(float2*)&S.Ps[w][gid + 8][nt * 8 + 2 * tig] = make_float2(tfr(p2), tfr(p3));
            }
            sumA += __shfl_xor_sync(0xffffffffu, sumA, 1);
            sumA += __shfl_xor_sync(0xffffffffu, sumA, 2);
            sumB += __shfl_xor_sync(0xffffffffu, sumB, 1);
            sumB += __shfl_xor_sync(0xffffffffu, sumB, 2);
            l_runA = l_runA * aA + sumA;
            l_runB = l_runB * aB + sumB;

            // rescale O
#pragma unroll
            for (int nt = 0; nt < 16; nt++) {
                o[nt][0] *= aA; o[nt][1] *= aA;
                o[nt][2] *= aB; o[nt][3] *= aB;
            }
            __syncwarp();

            // ---- O += P V ----
#pragma unroll
            for (int k8 = 0; k8 < 8; k8++) {
                unsigned a0 = __float_as_uint(S.Ps[w][gid][k8 * 8 + tig]);
                unsigned a1 = __float_as_uint(S.Ps[w][gid + 8][k8 * 8 + tig]);
                unsigned a2 = __float_as_uint(S.Ps[w][gid][k8 * 8 + tig + 4]);
                unsigned a3 = __float_as_uint(S.Ps[w][gid + 8][k8 * 8 + tig + 4]);
#pragma unroll
                for (int nt = 0; nt < 16; nt++) {
                    unsigned b0 = __float_as_uint(S.Vs[cur][k8 * 8 + tig][nt * 8 + gid]);
                    unsigned b1 = __float_as_uint(S.Vs[cur][k8 * 8 + tig + 4][nt * 8 + gid]);
                    mma_tf32(o[nt], a0, a1, a2, a3, b0, b1);
                }
            }
            __syncthreads();
        }

        // ---- final normalize + write ----
        const float iA = 1.f / l_runA;
        const float iB = 1.f / l_runB;
        const size_t obA = ((size_t)b * T_ + rowA) * H_;
        const size_t obB = ((size_t)b * T_ + rowB) * H_;
#pragma unroll
        for (int nt = 0; nt < 16; nt++) {
            const int c = nt * 8 + 2 * tig;
            *(float2*)&out[obA + c] = make_float2(o[nt][0] * iA, o[nt][1] * iA);
            *(float2*)&out[obB + c] = make_float2(o[nt][2] * iB, o[nt][3] * iB);
        }
    }
}

// ---------------------------------------------------------------------------
extern "C" void kernel_launch(void* const* d_in, const int* in_sizes, int n_in,
                              void* d_out, int out_size)
{
    const float* x  = (const float*)d_in[0];
    const float* Wq = (const float*)d_in[1];
    const float* Wk = (const float*)d_in[2];
    const float* Wv = (const float*)d_in[3];
    float* out = (float*)d_out;

    {
        dim3 grid(BT_ / 128, 3);
        qkv_mma<<<grid, 256>>>(x, Wq, Wk, Wv);
    }
    {
        static int smem_set = 0;
        const int smem_bytes = (int)sizeof(AttnSmem);
        if (!smem_set) {
            cudaFuncSetAttribute(attn_mma,
                                 cudaFuncAttributeMaxDynamicSharedMemorySize,
                                 smem_bytes);
            smem_set = 1;
        }
        dim3 grid(16, B_);
        attn_mma<<<grid, 128, smem_bytes>>>(out);
    }
}